// round 1
// baseline (speedup 1.0000x reference)
#include <cuda_runtime.h>
#include <cstdint>

// Problem constants
#define BATCH 2
#define L_SEQ 2048
#define CDIM  1024
#define HEADS 16
#define HD    64
#define MTOT  (BATCH * L_SEQ)       // 4096
#define THREEC (3 * CDIM)           // 3072
#define INV4  0.3535533905932738f   // 64^-0.25

// ---------------------------------------------------------------------------
// Scratch (device globals; no allocation allowed)
// ---------------------------------------------------------------------------
__device__ __align__(16) float g_qkv[(size_t)MTOT * THREEC];  // 48 MB
__device__ __align__(16) float g_q[(size_t)MTOT * CDIM];      // [B,H,L,D]
__device__ __align__(16) float g_k[(size_t)MTOT * CDIM];
__device__ __align__(16) float g_v[(size_t)MTOT * CDIM];
__device__ __align__(16) float g_att[(size_t)MTOT * CDIM];    // [B,L,H,D] = [4096,1024]

// ---------------------------------------------------------------------------
// GEMM: C[M,N] = A[M,K] * B[K,N], fp32, BM=128 BN=64 BK=16, 256 thr, 8x4 micro
// ---------------------------------------------------------------------------
__global__ __launch_bounds__(256) void gemm_kernel(
    const float* __restrict__ A, const float* __restrict__ B,
    float* __restrict__ C, int M, int N, int K)
{
    __shared__ float As[16][128];   // [k][m]
    __shared__ float Bs[16][64];    // [k][n]

    const int tid = threadIdx.x;
    const int tx = tid & 15;        // 0..15 -> n
    const int ty = tid >> 4;        // 0..15 -> m
    const int m0 = blockIdx.y * 128;
    const int n0 = blockIdx.x * 64;

    float acc[8][4];
#pragma unroll
    for (int i = 0; i < 8; i++)
#pragma unroll
        for (int j = 0; j < 4; j++) acc[i][j] = 0.f;

    for (int k0 = 0; k0 < K; k0 += 16) {
        // Load A tile 128x16 (512 float4s, 2 per thread), store transposed
#pragma unroll
        for (int i = 0; i < 2; i++) {
            int idx = tid + i * 256;
            int row = idx >> 2;
            int kc  = (idx & 3) << 2;
            float4 v = *(const float4*)&A[(size_t)(m0 + row) * K + k0 + kc];
            As[kc + 0][row] = v.x;
            As[kc + 1][row] = v.y;
            As[kc + 2][row] = v.z;
            As[kc + 3][row] = v.w;
        }
        // Load B tile 16x64 (256 float4s, 1 per thread)
        {
            int row = tid >> 4;
            int c   = (tid & 15) << 2;
            *(float4*)&Bs[row][c] = *(const float4*)&B[(size_t)(k0 + row) * N + n0 + c];
        }
        __syncthreads();

#pragma unroll
        for (int kk = 0; kk < 16; kk++) {
            float4 a0 = *(const float4*)&As[kk][ty * 8];
            float4 a1 = *(const float4*)&As[kk][ty * 8 + 4];
            float4 b  = *(const float4*)&Bs[kk][tx * 4];
            float av[8] = {a0.x, a0.y, a0.z, a0.w, a1.x, a1.y, a1.z, a1.w};
            float bv[4] = {b.x, b.y, b.z, b.w};
#pragma unroll
            for (int i = 0; i < 8; i++)
#pragma unroll
                for (int j = 0; j < 4; j++)
                    acc[i][j] = fmaf(av[i], bv[j], acc[i][j]);
        }
        __syncthreads();
    }

#pragma unroll
    for (int i = 0; i < 8; i++) {
        float4 v = make_float4(acc[i][0], acc[i][1], acc[i][2], acc[i][3]);
        *(float4*)&C[(size_t)(m0 + ty * 8 + i) * N + n0 + tx * 4] = v;
    }
}

// ---------------------------------------------------------------------------
// LayerNorm(q,k over head_dim) * D^-0.25 + split into [B,H,L,D] layouts
// One warp per (token m, head h).
// ---------------------------------------------------------------------------
__global__ __launch_bounds__(256) void ln_split_kernel(
    const float* __restrict__ qkv,
    const float* __restrict__ q_scale, const float* __restrict__ q_bias,
    const float* __restrict__ k_scale, const float* __restrict__ k_bias,
    float* __restrict__ q_t, float* __restrict__ k_t, float* __restrict__ v_t)
{
    const int wid  = (blockIdx.x * blockDim.x + threadIdx.x) >> 5;
    const int lane = threadIdx.x & 31;
    const int h = wid & (HEADS - 1);
    const int m = wid >> 4;              // 0..4095
    const int b = m >> 11;
    const int l = m & (L_SEQ - 1);

    const float* row = qkv + (size_t)m * THREEC;
    const size_t obase = (((size_t)(b * HEADS + h)) * L_SEQ + l) * HD;

    // --- q ---
    {
        float x0 = row[h * HD + lane];
        float x1 = row[h * HD + lane + 32];
        float s = x0 + x1;
#pragma unroll
        for (int o = 16; o > 0; o >>= 1) s += __shfl_xor_sync(0xffffffffu, s, o);
        float mu = s * (1.f / HD);
        float d0 = x0 - mu, d1 = x1 - mu;
        float vs = d0 * d0 + d1 * d1;
#pragma unroll
        for (int o = 16; o > 0; o >>= 1) vs += __shfl_xor_sync(0xffffffffu, vs, o);
        float rstd = rsqrtf(vs * (1.f / HD) + 1e-6f);
        q_t[obase + lane]      = (d0 * rstd * q_scale[lane]      + q_bias[lane])      * INV4;
        q_t[obase + lane + 32] = (d1 * rstd * q_scale[lane + 32] + q_bias[lane + 32]) * INV4;
    }
    // --- k ---
    {
        float x0 = row[CDIM + h * HD + lane];
        float x1 = row[CDIM + h * HD + lane + 32];
        float s = x0 + x1;
#pragma unroll
        for (int o = 16; o > 0; o >>= 1) s += __shfl_xor_sync(0xffffffffu, s, o);
        float mu = s * (1.f / HD);
        float d0 = x0 - mu, d1 = x1 - mu;
        float vs = d0 * d0 + d1 * d1;
#pragma unroll
        for (int o = 16; o > 0; o >>= 1) vs += __shfl_xor_sync(0xffffffffu, vs, o);
        float rstd = rsqrtf(vs * (1.f / HD) + 1e-6f);
        k_t[obase + lane]      = (d0 * rstd * k_scale[lane]      + k_bias[lane])      * INV4;
        k_t[obase + lane + 32] = (d1 * rstd * k_scale[lane + 32] + k_bias[lane + 32]) * INV4;
    }
    // --- v passthrough ---
    v_t[obase + lane]      = row[2 * CDIM + h * HD + lane];
    v_t[obase + lane + 32] = row[2 * CDIM + h * HD + lane + 32];
}

// ---------------------------------------------------------------------------
// Flash attention: per (b,h), 128 query rows per block, 64-key tiles,
// online softmax. 256 threads, 8x4 micro tiles for S and O.
// Dyn smem: Qs[64][132] + KVs[64][68] + Ps[64][132] = 84,992 bytes.
// ---------------------------------------------------------------------------
#define QS_STRIDE 132
#define KV_STRIDE 68
#define PS_STRIDE 132
#define ATTN_SMEM_FLOATS (64 * QS_STRIDE + 64 * KV_STRIDE + 64 * PS_STRIDE)
#define ATTN_SMEM_BYTES  (ATTN_SMEM_FLOATS * 4)

__global__ __launch_bounds__(256, 2) void attn_kernel(
    const float* __restrict__ q_t, const float* __restrict__ k_t,
    const float* __restrict__ v_t, float* __restrict__ att)
{
    extern __shared__ float sm[];
    float* Qs  = sm;                                 // [d][r]   64 x 132
    float* KVs = sm + 64 * QS_STRIDE;                // K: [d][c]; V: [c][d]  64 x 68
    float* Ps  = sm + 64 * QS_STRIDE + 64 * KV_STRIDE; // [c][r] 64 x 132

    const int tid = threadIdx.x;
    const int tx = tid & 15;       // key-col / d-col group
    const int ty = tid >> 4;       // q-row group (8 rows)
    const int bh = blockIdx.y;     // b*16 + h
    const int q0 = blockIdx.x * 128;

    const float* Q  = q_t + ((size_t)bh * L_SEQ + q0) * HD;
    const float* Kp = k_t + (size_t)bh * L_SEQ * HD;
    const float* Vp = v_t + (size_t)bh * L_SEQ * HD;

    // Load Q tile (128 rows x 64 d), transposed into Qs[d][r]
#pragma unroll
    for (int i = 0; i < 8; i++) {
        int idx = tid + i * 256;
        int r = idx >> 4;
        int d4 = (idx & 15) << 2;
        float4 v = *(const float4*)&Q[(size_t)r * HD + d4];
        Qs[(d4 + 0) * QS_STRIDE + r] = v.x;
        Qs[(d4 + 1) * QS_STRIDE + r] = v.y;
        Qs[(d4 + 2) * QS_STRIDE + r] = v.z;
        Qs[(d4 + 3) * QS_STRIDE + r] = v.w;
    }

    float m_i[8], l_i[8], O[8][4];
#pragma unroll
    for (int i = 0; i < 8; i++) {
        m_i[i] = -1e30f;
        l_i[i] = 0.f;
#pragma unroll
        for (int j = 0; j < 4; j++) O[i][j] = 0.f;
    }

    for (int kt = 0; kt < L_SEQ; kt += 64) {
        __syncthreads();
        // Load K tile transposed: KVs[d][c]
#pragma unroll
        for (int i = 0; i < 4; i++) {
            int idx = tid + i * 256;
            int c = idx >> 4;
            int d4 = (idx & 15) << 2;
            float4 v = *(const float4*)&Kp[(size_t)(kt + c) * HD + d4];
            KVs[(d4 + 0) * KV_STRIDE + c] = v.x;
            KVs[(d4 + 1) * KV_STRIDE + c] = v.y;
            KVs[(d4 + 2) * KV_STRIDE + c] = v.z;
            KVs[(d4 + 3) * KV_STRIDE + c] = v.w;
        }
        __syncthreads();

        // S = Q K^T  (rows ty*8+i, cols tx*4+j)
        float S[8][4];
#pragma unroll
        for (int i = 0; i < 8; i++)
#pragma unroll
            for (int j = 0; j < 4; j++) S[i][j] = 0.f;

#pragma unroll 8
        for (int d = 0; d < 64; d++) {
            float4 a0 = *(const float4*)&Qs[d * QS_STRIDE + ty * 8];
            float4 a1 = *(const float4*)&Qs[d * QS_STRIDE + ty * 8 + 4];
            float4 b  = *(const float4*)&KVs[d * KV_STRIDE + tx * 4];
            float av[8] = {a0.x, a0.y, a0.z, a0.w, a1.x, a1.y, a1.z, a1.w};
            float bv[4] = {b.x, b.y, b.z, b.w};
#pragma unroll
            for (int i = 0; i < 8; i++)
#pragma unroll
                for (int j = 0; j < 4; j++)
                    S[i][j] = fmaf(av[i], bv[j], S[i][j]);
        }

        // Online softmax per row (reduce across 16 tx lanes in half-warp)
#pragma unroll
        for (int i = 0; i < 8; i++) {
            float mx = fmaxf(fmaxf(S[i][0], S[i][1]), fmaxf(S[i][2], S[i][3]));
#pragma unroll
            for (int o = 8; o > 0; o >>= 1) mx = fmaxf(mx, __shfl_xor_sync(0xffffffffu, mx, o));
            float mn = fmaxf(m_i[i], mx);
            float alpha = __expf(m_i[i] - mn);
            m_i[i] = mn;
            float rs = 0.f;
#pragma unroll
            for (int j = 0; j < 4; j++) {
                float p = __expf(S[i][j] - mn);
                S[i][j] = p;
                rs += p;
            }
#pragma unroll
            for (int o = 8; o > 0; o >>= 1) rs += __shfl_xor_sync(0xffffffffu, rs, o);
            l_i[i] = l_i[i] * alpha + rs;
#pragma unroll
            for (int j = 0; j < 4; j++) O[i][j] *= alpha;
        }
        // Write P transposed [c][r] as float4 column segments
#pragma unroll
        for (int j = 0; j < 4; j++) {
            float4 p0 = make_float4(S[0][j], S[1][j], S[2][j], S[3][j]);
            float4 p1 = make_float4(S[4][j], S[5][j], S[6][j], S[7][j]);
            *(float4*)&Ps[(tx * 4 + j) * PS_STRIDE + ty * 8]     = p0;
            *(float4*)&Ps[(tx * 4 + j) * PS_STRIDE + ty * 8 + 4] = p1;
        }
        __syncthreads();

        // Load V tile natural: KVs[c][d]
#pragma unroll
        for (int i = 0; i < 4; i++) {
            int idx = tid + i * 256;
            int c = idx >> 4;
            int d4 = (idx & 15) << 2;
            *(float4*)&KVs[c * KV_STRIDE + d4] =
                *(const float4*)&Vp[(size_t)(kt + c) * HD + d4];
        }
        __syncthreads();

        // O += P V  (rows ty*8+i, d-cols tx*4+j)
#pragma unroll 8
        for (int c = 0; c < 64; c++) {
            float4 a0 = *(const float4*)&Ps[c * PS_STRIDE + ty * 8];
            float4 a1 = *(const float4*)&Ps[c * PS_STRIDE + ty * 8 + 4];
            float4 b  = *(const float4*)&KVs[c * KV_STRIDE + tx * 4];
            float av[8] = {a0.x, a0.y, a0.z, a0.w, a1.x, a1.y, a1.z, a1.w};
            float bv[4] = {b.x, b.y, b.z, b.w};
#pragma unroll
            for (int i = 0; i < 8; i++)
#pragma unroll
                for (int j = 0; j < 4; j++)
                    O[i][j] = fmaf(av[i], bv[j], O[i][j]);
        }
    }

    // Finalize + store to [B, L, H*D]
    const int b_ = bh >> 4;
    const int h  = bh & (HEADS - 1);
#pragma unroll
    for (int i = 0; i < 8; i++) {
        float inv = 1.f / l_i[i];
        float4 v = make_float4(O[i][0] * inv, O[i][1] * inv, O[i][2] * inv, O[i][3] * inv);
        int r = q0 + ty * 8 + i;
        *(float4*)&att[(((size_t)b_ * L_SEQ) + r) * CDIM + h * HD + tx * 4] = v;
    }
}

// ---------------------------------------------------------------------------
// Host launch
// ---------------------------------------------------------------------------
extern "C" void kernel_launch(void* const* d_in, const int* in_sizes, int n_in,
                              void* d_out, int out_size)
{
    const float* x       = (const float*)d_in[0];
    const float* w_qkv   = (const float*)d_in[1];
    const float* w_out   = (const float*)d_in[2];
    const float* q_scale = (const float*)d_in[3];
    const float* q_bias  = (const float*)d_in[4];
    const float* k_scale = (const float*)d_in[5];
    const float* k_bias  = (const float*)d_in[6];
    float* out = (float*)d_out;

    void *p_qkv, *p_q, *p_k, *p_v, *p_att;
    cudaGetSymbolAddress(&p_qkv, g_qkv);
    cudaGetSymbolAddress(&p_q, g_q);
    cudaGetSymbolAddress(&p_k, g_k);
    cudaGetSymbolAddress(&p_v, g_v);
    cudaGetSymbolAddress(&p_att, g_att);

    // 1) QKV projection: [4096,1024] x [1024,3072]
    gemm_kernel<<<dim3(THREEC / 64, MTOT / 128), 256>>>(
        x, w_qkv, (float*)p_qkv, MTOT, THREEC, CDIM);

    // 2) QK LayerNorm + head split (one warp per token-head)
    ln_split_kernel<<<(MTOT * HEADS) / 8, 256>>>(
        (const float*)p_qkv, q_scale, q_bias, k_scale, k_bias,
        (float*)p_q, (float*)p_k, (float*)p_v);

    // 3) Flash attention
    cudaFuncSetAttribute(attn_kernel, cudaFuncAttributeMaxDynamicSharedMemorySize,
                         ATTN_SMEM_BYTES);
    attn_kernel<<<dim3(L_SEQ / 128, BATCH * HEADS), 256, ATTN_SMEM_BYTES>>>(
        (const float*)p_q, (const float*)p_k, (const float*)p_v, (float*)p_att);

    // 4) Output projection: [4096,1024] x [1024,1024]
    gemm_kernel<<<dim3(CDIM / 64, MTOT / 128), 256>>>(
        (const float*)p_att, w_out, out, MTOT, CDIM, CDIM);
}

// round 2
// speedup vs baseline: 2.4189x; 2.4189x over previous
#include <cuda_runtime.h>
#include <cstdint>

// Problem constants
#define BATCH 2
#define L_SEQ 2048
#define CDIM  1024
#define HEADS 16
#define HD    64
#define MTOT  (BATCH * L_SEQ)       // 4096
#define THREEC (3 * CDIM)           // 3072
#define INV4  0.3535533905932738f   // 64^-0.25

// ---------------------------------------------------------------------------
// Scratch (device globals; no allocation allowed)
// ---------------------------------------------------------------------------
__device__ __align__(16) float g_qkv[(size_t)MTOT * THREEC];  // 48 MB
__device__ __align__(16) float g_q[(size_t)MTOT * CDIM];      // [B,H,L,D]
__device__ __align__(16) float g_k[(size_t)MTOT * CDIM];
__device__ __align__(16) float g_v[(size_t)MTOT * CDIM];
__device__ __align__(16) float g_att[(size_t)MTOT * CDIM];    // [B,L,H*D]

// ---------------------------------------------------------------------------
// Helpers
// ---------------------------------------------------------------------------
__device__ __forceinline__ uint32_t f2tf32(float f) {
    uint32_t r;
    asm("cvt.rna.tf32.f32 %0, %1;" : "=r"(r) : "f"(f));
    return r;
}

__device__ __forceinline__ void mma_tf32(float* d,
                                         uint32_t a0, uint32_t a1, uint32_t a2, uint32_t a3,
                                         uint32_t b0, uint32_t b1) {
    asm volatile(
        "mma.sync.aligned.m16n8k8.row.col.f32.tf32.tf32.f32 "
        "{%0,%1,%2,%3}, {%4,%5,%6,%7}, {%8,%9}, {%0,%1,%2,%3};\n"
        : "+f"(d[0]), "+f"(d[1]), "+f"(d[2]), "+f"(d[3])
        : "r"(a0), "r"(a1), "r"(a2), "r"(a3), "r"(b0), "r"(b1));
}

// pair-permutation within each 8-column group: col c -> (c%4)*2 + (c/4)%2
// maps (t, t+4) -> adjacent (2t, 2t+1) so B fragments load as one LDS.64
__device__ __forceinline__ int pair_perm(int c) {
    return (c & ~7) | (((c & 3) << 1) | ((c >> 2) & 1));
}

// ---------------------------------------------------------------------------
// TF32 tensor-core GEMM: C[M,N] = A[M,K]*B[K,N]
// BM=BN=128, BK=16, 256 threads (8 warps, each 64x32)
// ---------------------------------------------------------------------------
#define AS_STR 17
#define BS_STR 136

__global__ __launch_bounds__(256) void gemm_tf32_kernel(
    const float* __restrict__ A, const float* __restrict__ B,
    float* __restrict__ C, int M, int N, int K)
{
    __shared__ float As[128 * AS_STR];   // [m][k], tf32-rounded
    __shared__ float Bs[16 * BS_STR];    // [k][n], tf32-rounded

    const int tid  = threadIdx.x;
    const int w    = tid >> 5;
    const int lane = tid & 31;
    const int g = lane >> 2;     // group (row)
    const int t = lane & 3;      // thread-in-group (col)
    const int wm = (w & 1) * 64;
    const int wn = (w >> 1) * 32;
    const int m0 = blockIdx.y * 128;
    const int n0 = blockIdx.x * 128;

    // tile-load assignments
    const int a_row = tid >> 1;           // 0..127
    const int a_k   = (tid & 1) * 8;      // 0 or 8
    const int b_row = tid >> 4;           // 0..15
    const int b_c   = (tid & 15) * 8;     // 0..120

    float acc[4][4][4];
#pragma unroll
    for (int i = 0; i < 4; i++)
#pragma unroll
        for (int j = 0; j < 4; j++)
#pragma unroll
            for (int v = 0; v < 4; v++) acc[i][j][v] = 0.f;

    float4 pa0, pa1, pb0, pb1;
    // prefetch tile 0
    pa0 = *(const float4*)&A[(size_t)(m0 + a_row) * K + a_k];
    pa1 = *(const float4*)&A[(size_t)(m0 + a_row) * K + a_k + 4];
    pb0 = *(const float4*)&B[(size_t)b_row * N + n0 + b_c];
    pb1 = *(const float4*)&B[(size_t)b_row * N + n0 + b_c + 4];

    // store tile 0 (tf32-rounded)
    {
        float* ap = &As[a_row * AS_STR + a_k];
        ap[0] = __uint_as_float(f2tf32(pa0.x)); ap[1] = __uint_as_float(f2tf32(pa0.y));
        ap[2] = __uint_as_float(f2tf32(pa0.z)); ap[3] = __uint_as_float(f2tf32(pa0.w));
        ap[4] = __uint_as_float(f2tf32(pa1.x)); ap[5] = __uint_as_float(f2tf32(pa1.y));
        ap[6] = __uint_as_float(f2tf32(pa1.z)); ap[7] = __uint_as_float(f2tf32(pa1.w));
        float* bp = &Bs[b_row * BS_STR + b_c];
        bp[0] = __uint_as_float(f2tf32(pb0.x)); bp[1] = __uint_as_float(f2tf32(pb0.y));
        bp[2] = __uint_as_float(f2tf32(pb0.z)); bp[3] = __uint_as_float(f2tf32(pb0.w));
        bp[4] = __uint_as_float(f2tf32(pb1.x)); bp[5] = __uint_as_float(f2tf32(pb1.y));
        bp[6] = __uint_as_float(f2tf32(pb1.z)); bp[7] = __uint_as_float(f2tf32(pb1.w));
    }
    __syncthreads();

    for (int k0 = 0; k0 < K; k0 += 16) {
        const bool has_next = (k0 + 16 < K);
        if (has_next) {
            pa0 = *(const float4*)&A[(size_t)(m0 + a_row) * K + k0 + 16 + a_k];
            pa1 = *(const float4*)&A[(size_t)(m0 + a_row) * K + k0 + 16 + a_k + 4];
            pb0 = *(const float4*)&B[(size_t)(k0 + 16 + b_row) * N + n0 + b_c];
            pb1 = *(const float4*)&B[(size_t)(k0 + 16 + b_row) * N + n0 + b_c + 4];
        }

#pragma unroll
        for (int ks = 0; ks < 2; ks++) {
            uint32_t af[4][4], bf[4][2];
#pragma unroll
            for (int mt = 0; mt < 4; mt++) {
                const float* base = &As[(wm + mt * 16 + g) * AS_STR + ks * 8 + t];
                af[mt][0] = __float_as_uint(base[0]);
                af[mt][1] = __float_as_uint(base[8 * AS_STR]);
                af[mt][2] = __float_as_uint(base[4]);
                af[mt][3] = __float_as_uint(base[8 * AS_STR + 4]);
            }
#pragma unroll
            for (int nt = 0; nt < 4; nt++) {
                const float* base = &Bs[(ks * 8 + t) * BS_STR + wn + nt * 8 + g];
                bf[nt][0] = __float_as_uint(base[0]);
                bf[nt][1] = __float_as_uint(base[4 * BS_STR]);
            }
#pragma unroll
            for (int mt = 0; mt < 4; mt++)
#pragma unroll
                for (int nt = 0; nt < 4; nt++)
                    mma_tf32(acc[mt][nt], af[mt][0], af[mt][1], af[mt][2], af[mt][3],
                             bf[nt][0], bf[nt][1]);
        }
        __syncthreads();

        if (has_next) {
            float* ap = &As[a_row * AS_STR + a_k];
            ap[0] = __uint_as_float(f2tf32(pa0.x)); ap[1] = __uint_as_float(f2tf32(pa0.y));
            ap[2] = __uint_as_float(f2tf32(pa0.z)); ap[3] = __uint_as_float(f2tf32(pa0.w));
            ap[4] = __uint_as_float(f2tf32(pa1.x)); ap[5] = __uint_as_float(f2tf32(pa1.y));
            ap[6] = __uint_as_float(f2tf32(pa1.z)); ap[7] = __uint_as_float(f2tf32(pa1.w));
            float* bp = &Bs[b_row * BS_STR + b_c];
            bp[0] = __uint_as_float(f2tf32(pb0.x)); bp[1] = __uint_as_float(f2tf32(pb0.y));
            bp[2] = __uint_as_float(f2tf32(pb0.z)); bp[3] = __uint_as_float(f2tf32(pb0.w));
            bp[4] = __uint_as_float(f2tf32(pb1.x)); bp[5] = __uint_as_float(f2tf32(pb1.y));
            bp[6] = __uint_as_float(f2tf32(pb1.z)); bp[7] = __uint_as_float(f2tf32(pb1.w));
            __syncthreads();
        }
    }

    // epilogue: each fragment row writes float2 at cols 2t, 2t+1
#pragma unroll
    for (int mt = 0; mt < 4; mt++) {
        const int row = m0 + wm + mt * 16 + g;
#pragma unroll
        for (int nt = 0; nt < 4; nt++) {
            const int col = n0 + wn + nt * 8 + 2 * t;
            float2 v0 = make_float2(acc[mt][nt][0], acc[mt][nt][1]);
            float2 v1 = make_float2(acc[mt][nt][2], acc[mt][nt][3]);
            *(float2*)&C[(size_t)row * N + col] = v0;
            *(float2*)&C[(size_t)(row + 8) * N + col] = v1;
        }
    }
}

// ---------------------------------------------------------------------------
// LayerNorm(q,k over head_dim)*D^-0.25 + split; outputs tf32-rounded
// ---------------------------------------------------------------------------
__global__ __launch_bounds__(256) void ln_split_kernel(
    const float* __restrict__ qkv,
    const float* __restrict__ q_scale, const float* __restrict__ q_bias,
    const float* __restrict__ k_scale, const float* __restrict__ k_bias,
    float* __restrict__ q_t, float* __restrict__ k_t, float* __restrict__ v_t)
{
    const int wid  = (blockIdx.x * blockDim.x + threadIdx.x) >> 5;
    const int lane = threadIdx.x & 31;
    const int h = wid & (HEADS - 1);
    const int m = wid >> 4;              // 0..4095
    const int b = m >> 11;
    const int l = m & (L_SEQ - 1);

    const float* row = qkv + (size_t)m * THREEC;
    const size_t obase = (((size_t)(b * HEADS + h)) * L_SEQ + l) * HD;

    // --- q ---
    {
        float x0 = row[h * HD + lane];
        float x1 = row[h * HD + lane + 32];
        float s = x0 + x1;
#pragma unroll
        for (int o = 16; o > 0; o >>= 1) s += __shfl_xor_sync(0xffffffffu, s, o);
        float mu = s * (1.f / HD);
        float d0 = x0 - mu, d1 = x1 - mu;
        float vs = d0 * d0 + d1 * d1;
#pragma unroll
        for (int o = 16; o > 0; o >>= 1) vs += __shfl_xor_sync(0xffffffffu, vs, o);
        float rstd = rsqrtf(vs * (1.f / HD) + 1e-6f);
        q_t[obase + lane] =
            __uint_as_float(f2tf32((d0 * rstd * q_scale[lane] + q_bias[lane]) * INV4));
        q_t[obase + lane + 32] =
            __uint_as_float(f2tf32((d1 * rstd * q_scale[lane + 32] + q_bias[lane + 32]) * INV4));
    }
    // --- k ---
    {
        float x0 = row[CDIM + h * HD + lane];
        float x1 = row[CDIM + h * HD + lane + 32];
        float s = x0 + x1;
#pragma unroll
        for (int o = 16; o > 0; o >>= 1) s += __shfl_xor_sync(0xffffffffu, s, o);
        float mu = s * (1.f / HD);
        float d0 = x0 - mu, d1 = x1 - mu;
        float vs = d0 * d0 + d1 * d1;
#pragma unroll
        for (int o = 16; o > 0; o >>= 1) vs += __shfl_xor_sync(0xffffffffu, vs, o);
        float rstd = rsqrtf(vs * (1.f / HD) + 1e-6f);
        k_t[obase + lane] =
            __uint_as_float(f2tf32((d0 * rstd * k_scale[lane] + k_bias[lane]) * INV4));
        k_t[obase + lane + 32] =
            __uint_as_float(f2tf32((d1 * rstd * k_scale[lane + 32] + k_bias[lane + 32]) * INV4));
    }
    // --- v (tf32-rounded passthrough) ---
    v_t[obase + lane]      = __uint_as_float(f2tf32(row[2 * CDIM + h * HD + lane]));
    v_t[obase + lane + 32] = __uint_as_float(f2tf32(row[2 * CDIM + h * HD + lane + 32]));
}

// ---------------------------------------------------------------------------
// Flash attention with tf32 tensor cores.
// 128 q-rows/CTA, 8 warps x 16 rows, 64-key tiles.
// Ks: [key][d-pair-permuted] stride 72 (B-frag = one LDS.64, conflict-free)
// Vs: [key][d] natural, stride 68 (scalar B-frag loads)
// ---------------------------------------------------------------------------
#define KS_STR 72
#define VS_STR 68

__global__ __launch_bounds__(256, 2) void attn_mma_kernel(
    const float* __restrict__ q_t, const float* __restrict__ k_t,
    const float* __restrict__ v_t, float* __restrict__ att)
{
    __shared__ float Ks[64 * KS_STR];
    __shared__ float Vs[64 * VS_STR];

    const int tid  = threadIdx.x;
    const int w    = tid >> 5;
    const int lane = tid & 31;
    const int g = lane >> 2;
    const int t = lane & 3;
    const int bh = blockIdx.y;          // b*16 + h
    const int q0 = blockIdx.x * 128;
    const int qrow = q0 + w * 16;

    const float* Qp = q_t + (size_t)bh * L_SEQ * HD;
    const float* Kp = k_t + (size_t)bh * L_SEQ * HD;
    const float* Vp = v_t + (size_t)bh * L_SEQ * HD;

    // Q A-fragments in registers for the whole loop (already tf32 in gmem)
    uint32_t qa[8][4];
#pragma unroll
    for (int kk = 0; kk < 8; kk++) {
        qa[kk][0] = __float_as_uint(Qp[(size_t)(qrow + g)     * HD + kk * 8 + t]);
        qa[kk][1] = __float_as_uint(Qp[(size_t)(qrow + g + 8) * HD + kk * 8 + t]);
        qa[kk][2] = __float_as_uint(Qp[(size_t)(qrow + g)     * HD + kk * 8 + t + 4]);
        qa[kk][3] = __float_as_uint(Qp[(size_t)(qrow + g + 8) * HD + kk * 8 + t + 4]);
    }

    float o[8][4];
#pragma unroll
    for (int nn = 0; nn < 8; nn++)
#pragma unroll
        for (int v = 0; v < 4; v++) o[nn][v] = 0.f;
    float mrow0 = -1e30f, mrow1 = -1e30f;   // running max for rows g, g+8
    float lrow0 = 0.f,    lrow1 = 0.f;

    for (int kt = 0; kt < L_SEQ; kt += 64) {
        __syncthreads();
        // load K tile [64 keys][64 d] -> Ks[key][perm(d)]; V natural
#pragma unroll
        for (int i = 0; i < 4; i++) {
            int idx = tid + i * 256;
            int key = idx >> 4;
            int d4  = (idx & 15) << 2;
            float4 kv = *(const float4*)&Kp[(size_t)(kt + key) * HD + d4];
            Ks[key * KS_STR + pair_perm(d4 + 0)] = kv.x;
            Ks[key * KS_STR + pair_perm(d4 + 1)] = kv.y;
            Ks[key * KS_STR + pair_perm(d4 + 2)] = kv.z;
            Ks[key * KS_STR + pair_perm(d4 + 3)] = kv.w;
            float4 vv = *(const float4*)&Vp[(size_t)(kt + key) * HD + d4];
            *(float4*)&Vs[key * VS_STR + d4] = vv;
        }
        __syncthreads();

        // S = Q K^T : per warp 16x64, 8 n-tiles x 8 k-tiles
        float s[8][4];
#pragma unroll
        for (int nn = 0; nn < 8; nn++)
#pragma unroll
            for (int v = 0; v < 4; v++) s[nn][v] = 0.f;

#pragma unroll
        for (int nn = 0; nn < 8; nn++) {
#pragma unroll
            for (int kk = 0; kk < 8; kk++) {
                float2 b = *(const float2*)&Ks[(nn * 8 + g) * KS_STR + kk * 8 + 2 * t];
                mma_tf32(s[nn], qa[kk][0], qa[kk][1], qa[kk][2], qa[kk][3],
                         __float_as_uint(b.x), __float_as_uint(b.y));
            }
        }

        // online softmax (rows g and g+8, reductions within 4-lane quad)
        float mx0 = -1e30f, mx1 = -1e30f;
#pragma unroll
        for (int nn = 0; nn < 8; nn++) {
            mx0 = fmaxf(mx0, fmaxf(s[nn][0], s[nn][1]));
            mx1 = fmaxf(mx1, fmaxf(s[nn][2], s[nn][3]));
        }
        mx0 = fmaxf(mx0, __shfl_xor_sync(0xffffffffu, mx0, 1));
        mx0 = fmaxf(mx0, __shfl_xor_sync(0xffffffffu, mx0, 2));
        mx1 = fmaxf(mx1, __shfl_xor_sync(0xffffffffu, mx1, 1));
        mx1 = fmaxf(mx1, __shfl_xor_sync(0xffffffffu, mx1, 2));

        float mn0 = fmaxf(mrow0, mx0);
        float mn1 = fmaxf(mrow1, mx1);
        float alpha0 = __expf(mrow0 - mn0);
        float alpha1 = __expf(mrow1 - mn1);
        mrow0 = mn0; mrow1 = mn1;

        float rs0 = 0.f, rs1 = 0.f;
#pragma unroll
        for (int nn = 0; nn < 8; nn++) {
            float p0 = __expf(s[nn][0] - mn0);
            float p1 = __expf(s[nn][1] - mn0);
            float p2 = __expf(s[nn][2] - mn1);
            float p3 = __expf(s[nn][3] - mn1);
            rs0 += p0 + p1;
            rs1 += p2 + p3;
            // round P to tf32 for the PV mma
            s[nn][0] = __uint_as_float(f2tf32(p0));
            s[nn][1] = __uint_as_float(f2tf32(p1));
            s[nn][2] = __uint_as_float(f2tf32(p2));
            s[nn][3] = __uint_as_float(f2tf32(p3));
        }
        rs0 += __shfl_xor_sync(0xffffffffu, rs0, 1);
        rs0 += __shfl_xor_sync(0xffffffffu, rs0, 2);
        rs1 += __shfl_xor_sync(0xffffffffu, rs1, 1);
        rs1 += __shfl_xor_sync(0xffffffffu, rs1, 2);
        lrow0 = lrow0 * alpha0 + rs0;
        lrow1 = lrow1 * alpha1 + rs1;

#pragma unroll
        for (int nn = 0; nn < 8; nn++) {
            o[nn][0] *= alpha0; o[nn][1] *= alpha0;
            o[nn][2] *= alpha1; o[nn][3] *= alpha1;
        }

        // O += P V : convert S C-frags -> A-frags via quad shuffles
        const int srcA = (lane & ~3) | (t >> 1);
        const int srcB = srcA + 2;
#pragma unroll
        for (int kk = 0; kk < 8; kk++) {
            float c0 = s[kk][0], c1 = s[kk][1], c2 = s[kk][2], c3 = s[kk][3];
            float e0  = __shfl_sync(0xffffffffu, c0, srcA);
            float o0_ = __shfl_sync(0xffffffffu, c1, srcA);
            float e0b = __shfl_sync(0xffffffffu, c0, srcB);
            float o0b = __shfl_sync(0xffffffffu, c1, srcB);
            float e1  = __shfl_sync(0xffffffffu, c2, srcA);
            float o1_ = __shfl_sync(0xffffffffu, c3, srcA);
            float e1b = __shfl_sync(0xffffffffu, c2, srcB);
            float o1b = __shfl_sync(0xffffffffu, c3, srcB);
            uint32_t a0 = __float_as_uint((t & 1) ? o0_ : e0);
            uint32_t a1 = __float_as_uint((t & 1) ? o1_ : e1);
            uint32_t a2 = __float_as_uint((t & 1) ? o0b : e0b);
            uint32_t a3 = __float_as_uint((t & 1) ? o1b : e1b);
#pragma unroll
            for (int nn = 0; nn < 8; nn++) {
                uint32_t b0 = __float_as_uint(Vs[(kk * 8 + t)     * VS_STR + nn * 8 + g]);
                uint32_t b1 = __float_as_uint(Vs[(kk * 8 + t + 4) * VS_STR + nn * 8 + g]);
                mma_tf32(o[nn], a0, a1, a2, a3, b0, b1);
            }
        }
    }

    // finalize + store to [B, L, H*D]
    const int b_ = bh >> 4;
    const int h  = bh & (HEADS - 1);
    const float inv0 = 1.f / lrow0;
    const float inv1 = 1.f / lrow1;
    const size_t base0 = ((size_t)b_ * L_SEQ + qrow + g)     * CDIM + h * HD;
    const size_t base1 = ((size_t)b_ * L_SEQ + qrow + g + 8) * CDIM + h * HD;
#pragma unroll
    for (int nn = 0; nn < 8; nn++) {
        *(float2*)&att[base0 + nn * 8 + 2 * t] = make_float2(o[nn][0] * inv0, o[nn][1] * inv0);
        *(float2*)&att[base1 + nn * 8 + 2 * t] = make_float2(o[nn][2] * inv1, o[nn][3] * inv1);
    }
}

// ---------------------------------------------------------------------------
// Host launch
// ---------------------------------------------------------------------------
extern "C" void kernel_launch(void* const* d_in, const int* in_sizes, int n_in,
                              void* d_out, int out_size)
{
    const float* x       = (const float*)d_in[0];
    const float* w_qkv   = (const float*)d_in[1];
    const float* w_out   = (const float*)d_in[2];
    const float* q_scale = (const float*)d_in[3];
    const float* q_bias  = (const float*)d_in[4];
    const float* k_scale = (const float*)d_in[5];
    const float* k_bias  = (const float*)d_in[6];
    float* out = (float*)d_out;

    void *p_qkv, *p_q, *p_k, *p_v, *p_att;
    cudaGetSymbolAddress(&p_qkv, g_qkv);
    cudaGetSymbolAddress(&p_q, g_q);
    cudaGetSymbolAddress(&p_k, g_k);
    cudaGetSymbolAddress(&p_v, g_v);
    cudaGetSymbolAddress(&p_att, g_att);

    // 1) QKV projection: [4096,1024] x [1024,3072]
    gemm_tf32_kernel<<<dim3(THREEC / 128, MTOT / 128), 256>>>(
        x, w_qkv, (float*)p_qkv, MTOT, THREEC, CDIM);

    // 2) QK LayerNorm + head split (tf32-rounded outputs)
    ln_split_kernel<<<(MTOT * HEADS) / 8, 256>>>(
        (const float*)p_qkv, q_scale, q_bias, k_scale, k_bias,
        (float*)p_q, (float*)p_k, (float*)p_v);

    // 3) Flash attention (tensor cores)
    attn_mma_kernel<<<dim3(L_SEQ / 128, BATCH * HEADS), 256>>>(
        (const float*)p_q, (const float*)p_k, (const float*)p_v, (float*)p_att);

    // 4) Output projection: [4096,1024] x [1024,1024]
    gemm_tf32_kernel<<<dim3(CDIM / 128, MTOT / 128), 256>>>(
        (const float*)p_att, w_out, out, MTOT, CDIM, CDIM);
}